// round 13
// baseline (speedup 1.0000x reference)
#include <cuda_runtime.h>
#include <cuda_bf16.h>
#include <mma.h>
#include <math.h>
#include <stdint.h>

using namespace nvcuda;

#define BN_EPS 1e-5f

// ============================ scratch (device globals) ============================
__device__ __nv_bfloat16 g_w1s_hi[512 * 4096], g_w1s_lo[512 * 4096];
__device__ __nv_bfloat16 g_w2s_hi[128 * 512],  g_w2s_lo[128 * 512];
__device__ __nv_bfloat16 g_w1o_hi[128 * 1024], g_w1o_lo[128 * 1024];
__device__ __nv_bfloat16 g_w2o_hi[128 * 128],  g_w2o_lo[128 * 128];
__device__ __nv_bfloat16 g_w1b_hi[256 * 2048], g_w1b_lo[256 * 2048];
__device__ __nv_bfloat16 g_w2b_hi[128 * 256],  g_w2b_lo[128 * 256];
__device__ __nv_bfloat16 g_hs_hi[10240 * 512], g_hs_lo[10240 * 512];
__device__ __nv_bfloat16 g_ho_hi[10240 * 128], g_ho_lo[10240 * 128];
__device__ __nv_bfloat16 g_hb_hi[1024 * 256],  g_hb_lo[1024 * 256];
__device__ float g_obj[10240 * 128];
__device__ float g_sen[10240 * 128];
__device__ float g_bod[1024 * 128];
__device__ float g_xs[1024 * 688];
__device__ float g_bns_s[512], g_bns_t[512];
__device__ float g_bno_s[128], g_bno_t[128];
__device__ float g_bnb_s[256], g_bnb_t[256];
__device__ float g_bnf_s[256], g_bnf_t[256];

// ============================ helpers ============================
__device__ __forceinline__ void cp_async16(uint32_t saddr, const void* gptr) {
    asm volatile("cp.async.cg.shared.global [%0], [%1], 16;" :: "r"(saddr), "l"(gptr));
}
__device__ __forceinline__ uint32_t smem_u32(const void* p) {
    uint32_t a;
    asm("{ .reg .u64 t; cvta.to.shared.u64 t, %1; cvt.u32.u64 %0, t; }" : "=r"(a) : "l"(p));
    return a;
}
__device__ __forceinline__ void cp_commit() {
    asm volatile("cp.async.commit_group;" ::: "memory");
}
template<int N>
__device__ __forceinline__ void cp_wait() {
    asm volatile("cp.async.wait_group %0;" :: "n"(N) : "memory");
}

// ============================ BN fold prep ============================
__global__ void prep_bn_kernel(
    const float* __restrict__ gs, const float* __restrict__ bs,
    const float* __restrict__ ms, const float* __restrict__ vs,
    const float* __restrict__ go, const float* __restrict__ bo,
    const float* __restrict__ mo, const float* __restrict__ vo,
    const float* __restrict__ gb, const float* __restrict__ bb,
    const float* __restrict__ mb, const float* __restrict__ vb,
    const float* __restrict__ gf, const float* __restrict__ bfv,
    const float* __restrict__ mf, const float* __restrict__ vf,
    const float* __restrict__ bias_f)
{
    int i = threadIdx.x;
    if (i < 512) { float s = gs[i] * rsqrtf(vs[i] + BN_EPS); g_bns_s[i] = s; g_bns_t[i] = bs[i] - ms[i] * s; }
    if (i < 128) { float s = go[i] * rsqrtf(vo[i] + BN_EPS); g_bno_s[i] = s; g_bno_t[i] = bo[i] - mo[i] * s; }
    if (i < 256) { float s = gb[i] * rsqrtf(vb[i] + BN_EPS); g_bnb_s[i] = s; g_bnb_t[i] = bb[i] - mb[i] * s; }
    if (i < 256) { float s = gf[i] * rsqrtf(vf[i] + BN_EPS); g_bnf_s[i] = s; g_bnf_t[i] = (bias_f[i] - mf[i]) * s + bfv[i]; }
}

// ============================ all weight splits in one launch ============================
__global__ void split_all(
    const float4* __restrict__ W1s, const float4* __restrict__ W2s,
    const float4* __restrict__ W1o, const float4* __restrict__ W2o,
    const float4* __restrict__ W1b, const float4* __restrict__ W2b)
{
    int i = blockIdx.x * blockDim.x + threadIdx.x;
    const float4* src; uint2* hi; uint2* lo; int j;
    if (i < 524288)      { src = W1s; hi = (uint2*)g_w1s_hi; lo = (uint2*)g_w1s_lo; j = i; }
    else if (i < 540672) { src = W2s; hi = (uint2*)g_w2s_hi; lo = (uint2*)g_w2s_lo; j = i - 524288; }
    else if (i < 573440) { src = W1o; hi = (uint2*)g_w1o_hi; lo = (uint2*)g_w1o_lo; j = i - 540672; }
    else if (i < 577536) { src = W2o; hi = (uint2*)g_w2o_hi; lo = (uint2*)g_w2o_lo; j = i - 573440; }
    else if (i < 708608) { src = W1b; hi = (uint2*)g_w1b_hi; lo = (uint2*)g_w1b_lo; j = i - 577536; }
    else if (i < 716800) { src = W2b; hi = (uint2*)g_w2b_hi; lo = (uint2*)g_w2b_lo; j = i - 708608; }
    else return;
    float4 v = src[j];
    union { __nv_bfloat16 h[4]; uint2 u; } H, L;
    H.h[0] = __float2bfloat16(v.x); L.h[0] = __float2bfloat16(v.x - __bfloat162float(H.h[0]));
    H.h[1] = __float2bfloat16(v.y); L.h[1] = __float2bfloat16(v.y - __bfloat162float(H.h[1]));
    H.h[2] = __float2bfloat16(v.z); L.h[2] = __float2bfloat16(v.z - __bfloat162float(H.h[2]));
    H.h[3] = __float2bfloat16(v.w); L.h[3] = __float2bfloat16(v.w - __bfloat162float(H.h[3]));
    hi[j] = H.u; lo[j] = L.u;
}

// ============================ fused-split bf16x3 GEMM core (GEMM1, 512 threads / 16 warps) ============================
// Same R9 pipeline (A double-buffered planes, 1 barrier/chunk, stsA overlap), but
// 16 warps in 4x4 layout (warp tile 32x32) for 2x latency hiding per SMSP.
// SMEM: Ahi0|Alo0|Ahi1|Alo1|Bhi0|Blo0|Bhi1|Blo1 = 8 * 18432 = 147456 B.
template<int K, bool BN_RELU>
__device__ __forceinline__ void fgemm_dev(
    int N_TOT, int bm0, int bn0,
    const float* __restrict__ A32,
    const __nv_bfloat16* __restrict__ Bhi, const __nv_bfloat16* __restrict__ Blo,
    float* __restrict__ Cf,
    __nv_bfloat16* __restrict__ Chi, __nv_bfloat16* __restrict__ Clo,
    const float* __restrict__ sc, const float* __restrict__ sh,
    char* smraw)
{
    constexpr int KITERS = K / 64;
    constexpr int LDT = 72;
    constexpr int PL = 128 * LDT * 2;     // 18432 B per plane
    const uint32_t sbase = smem_u32(smraw);

    const int tid = threadIdx.x;
    const int wid = tid >> 5;
    const int lane = tid & 31;
    const int warp_m = wid & 3;           // 4 slabs of 32 rows
    const int warp_n = wid >> 2;          // 4 slabs of 32 cols

    wmma::fragment<wmma::accumulator, 16, 16, 16, float> c[2][2];
#pragma unroll
    for (int mi = 0; mi < 2; mi++)
#pragma unroll
        for (int ni = 0; ni < 2; ni++) wmma::fill_fragment(c[mi][ni], 0.0f);

    const int lr = tid >> 3;              // 0..63
    const int lq = tid & 7;

    float4 areg[4];                       // 2 rows x 8 floats

    auto ldgA = [&](int cix) {
#pragma unroll
        for (int i = 0; i < 2; i++) {
            const float* p = A32 + (size_t)(bm0 + lr + i * 64) * K + cix * 64 + lq * 8;
            areg[i * 2]     = *reinterpret_cast<const float4*>(p);
            areg[i * 2 + 1] = *reinterpret_cast<const float4*>(p + 4);
        }
    };
    auto cpB = [&](int cix, int s) {
        const uint32_t bh = sbase + 4 * PL + s * 2 * PL;
        const uint32_t bl = bh + PL;
#pragma unroll
        for (int i = 0; i < 2; i++) {
            int r = lr + i * 64;
            cp_async16(bh + r * (LDT * 2) + lq * 16, Bhi + (size_t)(bn0 + r) * K + cix * 64 + lq * 8);
            cp_async16(bl + r * (LDT * 2) + lq * 16, Blo + (size_t)(bn0 + r) * K + cix * 64 + lq * 8);
        }
        cp_commit();
    };
    auto stsA = [&](int s) {
        char* ah = smraw + s * 2 * PL;
        char* al = ah + PL;
#pragma unroll
        for (int i = 0; i < 2; i++) {
            int r = lr + i * 64;
            float f[8] = { areg[i*2].x, areg[i*2].y, areg[i*2].z, areg[i*2].w,
                           areg[i*2+1].x, areg[i*2+1].y, areg[i*2+1].z, areg[i*2+1].w };
            union { __nv_bfloat16 h[8]; uint4 u; } H, L;
#pragma unroll
            for (int j = 0; j < 8; j++) {
                H.h[j] = __float2bfloat16(f[j]);
                L.h[j] = __float2bfloat16(f[j] - __bfloat162float(H.h[j]));
            }
            *reinterpret_cast<uint4*>(ah + r * (LDT * 2) + lq * 16) = H.u;
            *reinterpret_cast<uint4*>(al + r * (LDT * 2) + lq * 16) = L.u;
        }
    };

    // prologue
    ldgA(0);
    cpB(0, 0);
    stsA(0);
    if (KITERS > 1) ldgA(1);

    for (int cix = 0; cix < KITERS; ++cix) {
        const int s = cix & 1;
        cp_wait<0>();          // B(cix) resident
        __syncthreads();       // all warps: stsA(cix) done, mma(cix-1) done
        if (cix + 1 < KITERS) cpB(cix + 1, s ^ 1);

        const __nv_bfloat16* ah = reinterpret_cast<const __nv_bfloat16*>(smraw + s * 2 * PL);
        const __nv_bfloat16* al = ah + PL / 2;
        const __nv_bfloat16* bh = reinterpret_cast<const __nv_bfloat16*>(smraw + 4 * PL + s * 2 * PL);
        const __nv_bfloat16* bl = bh + PL / 2;
#pragma unroll
        for (int kk = 0; kk < 4; kk++) {
            wmma::fragment<wmma::matrix_a, 16, 16, 16, __nv_bfloat16, wmma::row_major> a_hi[2], a_lo[2];
            wmma::fragment<wmma::matrix_b, 16, 16, 16, __nv_bfloat16, wmma::col_major> b_hi[2], b_lo[2];
#pragma unroll
            for (int mi = 0; mi < 2; mi++) {
                wmma::load_matrix_sync(a_hi[mi], ah + (warp_m * 32 + mi * 16) * LDT + kk * 16, LDT);
                wmma::load_matrix_sync(a_lo[mi], al + (warp_m * 32 + mi * 16) * LDT + kk * 16, LDT);
            }
#pragma unroll
            for (int ni = 0; ni < 2; ni++) {
                wmma::load_matrix_sync(b_hi[ni], bh + (warp_n * 32 + ni * 16) * LDT + kk * 16, LDT);
                wmma::load_matrix_sync(b_lo[ni], bl + (warp_n * 32 + ni * 16) * LDT + kk * 16, LDT);
            }
#pragma unroll
            for (int mi = 0; mi < 2; mi++)
#pragma unroll
                for (int ni = 0; ni < 2; ni++) {
                    wmma::mma_sync(c[mi][ni], a_hi[mi], b_hi[ni], c[mi][ni]);
                    wmma::mma_sync(c[mi][ni], a_lo[mi], b_hi[ni], c[mi][ni]);
                    wmma::mma_sync(c[mi][ni], a_hi[mi], b_lo[ni], c[mi][ni]);
                }
        }
        if (cix + 1 < KITERS) {
            stsA(s ^ 1);                       // overlaps other warps' mma
            if (cix + 2 < KITERS) ldgA(cix + 2);
        }
    }
    __syncthreads();

    // epilogue: 16 warps x 32x36 f32 scratch (73728 B, fits in smem) 
    float* scr = reinterpret_cast<float*>(smraw) + wid * (32 * 36);
#pragma unroll
    for (int mi = 0; mi < 2; mi++)
#pragma unroll
        for (int ni = 0; ni < 2; ni++)
            wmma::store_matrix_sync(scr + mi * 16 * 36 + ni * 16, c[mi][ni], 36, wmma::mem_row_major);
    __syncwarp();

    const int col = bn0 + warp_n * 32 + lane;
#pragma unroll
    for (int rr = 0; rr < 32; rr++) {
        const size_t row = (size_t)(bm0 + warp_m * 32 + rr);
        float v = scr[rr * 36 + lane];
        if (BN_RELU) {
            v = fmaxf(fmaf(v, sc[col], sh[col]), 0.f);
            __nv_bfloat16 h = __float2bfloat16(v);
            Chi[row * N_TOT + col] = h;
            Clo[row * N_TOT + col] = __float2bfloat16(v - __bfloat162float(h));
        } else {
            Cf[row * N_TOT + col] = v;
        }
    }
}

// GEMM1 mega-kernel: sen1 (320) + obj1 (80) + body1 (16) = 416 CTAs, 512 threads
__global__ __launch_bounds__(512)
void gemm1_all(const float* __restrict__ sent, const float* __restrict__ feat,
               const float* __restrict__ body)
{
    extern __shared__ __align__(16) char smraw[];
    const int b = blockIdx.x;
    if (b < 320) {
        fgemm_dev<4096, true>(512, (b >> 2) * 128, (b & 3) * 128, sent,
                              g_w1s_hi, g_w1s_lo, nullptr, g_hs_hi, g_hs_lo,
                              g_bns_s, g_bns_t, smraw);
    } else if (b < 400) {
        fgemm_dev<1024, true>(128, (b - 320) * 128, 0, feat,
                              g_w1o_hi, g_w1o_lo, nullptr, g_ho_hi, g_ho_lo,
                              g_bno_s, g_bno_t, smraw);
    } else {
        const int bb = b - 400;
        fgemm_dev<2048, true>(256, (bb >> 1) * 128, (bb & 1) * 128, body,
                              g_w1b_hi, g_w1b_lo, nullptr, g_hb_hi, g_hb_lo,
                              g_bnb_s, g_bnb_t, smraw);
    }
}

// ============================ GEMM2: K-major 3-term, 4-plane chunks, double-buffered ============================
template<int K>
__device__ __forceinline__ void wmma_dev(
    int N_TOT, int bm0,
    const __nv_bfloat16* __restrict__ Ahi, const __nv_bfloat16* __restrict__ Alo,
    const __nv_bfloat16* __restrict__ Bhi, const __nv_bfloat16* __restrict__ Blo,
    float* __restrict__ Cf, char* smraw)
{
    constexpr int KITERS = K / 64;
    constexpr int LDT = 72;
    constexpr int PL = 128 * LDT * 2;      // 18432 B
    constexpr int STG = 4 * PL;
    const uint32_t sbase = smem_u32(smraw);

    const int tid = threadIdx.x;
    const int wid = tid >> 5;
    const int lane = tid & 31;
    const int warp_m = wid & 3;
    const int warp_n = wid >> 2;

    wmma::fragment<wmma::accumulator, 16, 16, 16, float> c[2][4];
#pragma unroll
    for (int mi = 0; mi < 2; mi++)
#pragma unroll
        for (int ni = 0; ni < 4; ni++) wmma::fill_fragment(c[mi][ni], 0.0f);

    const int lr = tid >> 3;
    const int lq = tid & 7;

    auto load_chunk = [&](int cix, int s) {
        const uint32_t base = sbase + s * STG;
#pragma unroll
        for (int i = 0; i < 4; i++) {
            int r = lr + i * 32;
            uint32_t off = r * (LDT * 2) + lq * 16;
            size_t ga = (size_t)(bm0 + r) * K + cix * 64 + lq * 8;
            size_t gb = (size_t)r * K + cix * 64 + lq * 8;
            cp_async16(base + off,          Ahi + ga);
            cp_async16(base + PL + off,     Alo + ga);
            cp_async16(base + 2 * PL + off, Bhi + gb);
            cp_async16(base + 3 * PL + off, Blo + gb);
        }
        cp_commit();
    };

    load_chunk(0, 0);
    for (int cix = 0; cix < KITERS; ++cix) {
        const int s = cix & 1;
        cp_wait<0>();
        __syncthreads();
        if (cix + 1 < KITERS) load_chunk(cix + 1, s ^ 1);

        const __nv_bfloat16* ah = reinterpret_cast<const __nv_bfloat16*>(smraw + s * STG);
        const __nv_bfloat16* al = ah + PL / 2;
        const __nv_bfloat16* bh = al + PL / 2;
        const __nv_bfloat16* bl = bh + PL / 2;
#pragma unroll
        for (int kk = 0; kk < 4; kk++) {
            wmma::fragment<wmma::matrix_a, 16, 16, 16, __nv_bfloat16, wmma::row_major> a_hi[2], a_lo[2];
            wmma::fragment<wmma::matrix_b, 16, 16, 16, __nv_bfloat16, wmma::col_major> b_hi[4], b_lo[4];
#pragma unroll
            for (int mi = 0; mi < 2; mi++) {
                wmma::load_matrix_sync(a_hi[mi], ah + (warp_m * 32 + mi * 16) * LDT + kk * 16, LDT);
                wmma::load_matrix_sync(a_lo[mi], al + (warp_m * 32 + mi * 16) * LDT + kk * 16, LDT);
            }
#pragma unroll
            for (int ni = 0; ni < 4; ni++) {
                wmma::load_matrix_sync(b_hi[ni], bh + (warp_n * 64 + ni * 16) * LDT + kk * 16, LDT);
                wmma::load_matrix_sync(b_lo[ni], bl + (warp_n * 64 + ni * 16) * LDT + kk * 16, LDT);
            }
#pragma unroll
            for (int mi = 0; mi < 2; mi++)
#pragma unroll
                for (int ni = 0; ni < 4; ni++) {
                    wmma::mma_sync(c[mi][ni], a_hi[mi], b_hi[ni], c[mi][ni]);
                    wmma::mma_sync(c[mi][ni], a_lo[mi], b_hi[ni], c[mi][ni]);
                    wmma::mma_sync(c[mi][ni], a_hi[mi], b_lo[ni], c[mi][ni]);
                }
        }
    }
    __syncthreads();

    float* scr = reinterpret_cast<float*>(smraw) + wid * (32 * 68);
#pragma unroll
    for (int mi = 0; mi < 2; mi++)
#pragma unroll
        for (int ni = 0; ni < 4; ni++)
            wmma::store_matrix_sync(scr + mi * 16 * 68 + ni * 16, c[mi][ni], 68, wmma::mem_row_major);
    __syncwarp();

#pragma unroll
    for (int cc = 0; cc < 2; cc++) {
        const int col = warp_n * 64 + cc * 32 + lane;
#pragma unroll
        for (int rr = 0; rr < 32; rr++) {
            const size_t row = (size_t)(bm0 + warp_m * 32 + rr);
            Cf[row * N_TOT + col] = scr[rr * 68 + cc * 32 + lane];
        }
    }
}

// GEMM2 mega-kernel: sen2 (80) + obj2 (80) + body2 (8) = 168 CTAs
__global__ __launch_bounds__(256)
void gemm2_all()
{
    extern __shared__ __align__(16) char smraw[];
    const int b = blockIdx.x;
    if (b < 80) {
        wmma_dev<512>(128, b * 128, g_hs_hi, g_hs_lo, g_w2s_hi, g_w2s_lo, g_sen, smraw);
    } else if (b < 160) {
        wmma_dev<128>(128, (b - 80) * 128, g_ho_hi, g_ho_lo, g_w2o_hi, g_w2o_lo, g_obj, smraw);
    } else {
        wmma_dev<256>(128, (b - 160) * 128, g_hb_hi, g_hb_lo, g_w2b_hi, g_w2b_lo, g_bod, smraw);
    }
}

// ============================ fp32 SGEMM (fc, K=688) ============================
template<int BM, int BN, int BK, int TM, int TN>
__global__ void sgemm_kernel(int M, int N, int K,
    const float* __restrict__ A, const float* __restrict__ B,
    float* __restrict__ C, int ldc,
    const float* __restrict__ sc, const float* __restrict__ sh)
{
    constexpr int THREADS = (BM / TM) * (BN / TN);
    __shared__ float As[BK][BM];
    __shared__ float Bs[BK][BN];
    const int tid = threadIdx.x;
    const int bn0 = blockIdx.x * BN;
    const int bm0 = blockIdx.y * BM;
    const int tx = tid % (BN / TN);
    const int ty = tid / (BN / TN);

    float acc[TM][TN];
#pragma unroll
    for (int i = 0; i < TM; i++)
#pragma unroll
        for (int j = 0; j < TN; j++) acc[i][j] = 0.f;

    constexpr int AV = BM * BK / 4 / THREADS;
    constexpr int BV = BN * BK / 4 / THREADS;

    for (int k0 = 0; k0 < K; k0 += BK) {
#pragma unroll
        for (int i = 0; i < AV; i++) {
            int idx = tid + i * THREADS;
            int r = idx / (BK / 4), c4 = idx % (BK / 4);
            float4 v = *reinterpret_cast<const float4*>(A + (size_t)(bm0 + r) * K + k0 + c4 * 4);
            As[c4 * 4 + 0][r] = v.x; As[c4 * 4 + 1][r] = v.y;
            As[c4 * 4 + 2][r] = v.z; As[c4 * 4 + 3][r] = v.w;
        }
#pragma unroll
        for (int i = 0; i < BV; i++) {
            int idx = tid + i * THREADS;
            int r = idx / (BK / 4), c4 = idx % (BK / 4);
            float4 v = *reinterpret_cast<const float4*>(B + (size_t)(bn0 + r) * K + k0 + c4 * 4);
            Bs[c4 * 4 + 0][r] = v.x; Bs[c4 * 4 + 1][r] = v.y;
            Bs[c4 * 4 + 2][r] = v.z; Bs[c4 * 4 + 3][r] = v.w;
        }
        __syncthreads();
#pragma unroll
        for (int kk = 0; kk < BK; kk++) {
            float a[TM], b[TN];
#pragma unroll
            for (int i = 0; i < TM; i += 4) {
                float4 v = *reinterpret_cast<const float4*>(&As[kk][ty * TM + i]);
                a[i] = v.x; a[i + 1] = v.y; a[i + 2] = v.z; a[i + 3] = v.w;
            }
#pragma unroll
            for (int j = 0; j < TN; j += 4) {
                float4 v = *reinterpret_cast<const float4*>(&Bs[kk][tx * TN + j]);
                b[j] = v.x; b[j + 1] = v.y; b[j + 2] = v.z; b[j + 3] = v.w;
            }
#pragma unroll
            for (int i = 0; i < TM; i++)
#pragma unroll
                for (int j = 0; j < TN; j++)
                    acc[i][j] = fmaf(a[i], b[j], acc[i][j]);
        }
        __syncthreads();
    }
#pragma unroll
    for (int i = 0; i < TM; i++) {
        int row = bm0 + ty * TM + i;
#pragma unroll
        for (int j = 0; j < TN; j++) {
            int col = bn0 + tx * TN + j;
            float v = acc[i][j];
            if (sc) v = fmaxf(fmaf(v, sc[col], sh[col]), 0.f);
            C[(size_t)row * ldc + col] = v;
        }
    }
}

// ============================ fused attention stage ============================
__global__ void attention_kernel(
    const float* __restrict__ bbox, const float* __restrict__ word,
    const float* __restrict__ Wc1, const float* __restrict__ Wc2,
    const float* __restrict__ Wsa)
{
    __shared__ float xt[10][688];
    __shared__ float rmean[10], rmax[10], att[10];
    __shared__ float csum[688], cmax[688];

    const int b = blockIdx.x;
    const int tid = threadIdx.x;

    for (int idx = tid; idx < 10 * 688; idx += blockDim.x) {
        int n = idx / 688, f = idx % 688;
        int rn = b * 10 + n;
        float v;
        if (f < 128)       v = g_obj[rn * 128 + f];
        else if (f < 132)  v = bbox[rn * 4 + (f - 128)];
        else if (f < 432)  v = word[rn * 300 + (f - 132)];
        else if (f < 560)  v = g_sen[rn * 128 + (f - 432)];
        else               v = g_bod[b * 128 + (f - 560)];
        xt[n][f] = v;
    }
    __syncthreads();

    int w = tid / 32, lane = tid % 32;
    if (w < 10) {
        float s = 0.f, mx = -3.402823e38f;
        for (int f = lane; f < 688; f += 32) {
            float v = xt[w][f];
            s += v; mx = fmaxf(mx, v);
        }
#pragma unroll
        for (int o = 16; o; o >>= 1) {
            s += __shfl_down_sync(0xffffffff, s, o);
            mx = fmaxf(mx, __shfl_down_sync(0xffffffff, mx, o));
        }
        if (lane == 0) { rmean[w] = s * (1.f / 688.f); rmax[w] = mx; }
    }
    __syncthreads();

    if (tid == 0) {
        float h[5], o1[10], o2[10];
        for (int j = 0; j < 5; j++) {
            float s = 0.f;
            for (int i = 0; i < 10; i++) s += rmean[i] * Wc1[j * 10 + i];
            h[j] = fmaxf(s, 0.f);
        }
        for (int n = 0; n < 10; n++) {
            float s = 0.f;
            for (int j = 0; j < 5; j++) s += h[j] * Wc2[n * 5 + j];
            o1[n] = s;
        }
        for (int j = 0; j < 5; j++) {
            float s = 0.f;
            for (int i = 0; i < 10; i++) s += rmax[i] * Wc1[j * 10 + i];
            h[j] = fmaxf(s, 0.f);
        }
        for (int n = 0; n < 10; n++) {
            float s = 0.f;
            for (int j = 0; j < 5; j++) s += h[j] * Wc2[n * 5 + j];
            o2[n] = s;
        }
        for (int n = 0; n < 10; n++)
            att[n] = 1.f / (1.f + expf(-(o1[n] + o2[n])));
    }
    __syncthreads();

    for (int f = tid; f < 688; f += blockDim.x) {
        float s = 0.f, mx = -3.402823e38f;
#pragma unroll
        for (int n = 0; n < 10; n++) {
            float v = xt[n][f] * att[n];
            s += v; mx = fmaxf(mx, v);
        }
        csum[f] = s; cmax[f] = mx;
    }
    __syncthreads();

    for (int f = tid; f < 688; f += blockDim.x) {
        float sa = 0.f;
#pragma unroll
        for (int j = 0; j < 7; j++) {
            int p = f + j - 3;
            if (p >= 0 && p < 688)
                sa += Wsa[j] * (csum[p] * 0.1f) + Wsa[7 + j] * cmax[p];
        }
        float sig = 1.f / (1.f + expf(-sa));
        g_xs[b * 688 + f] = csum[f] * sig;
    }
}

// ============================ launch ============================
extern "C" void kernel_launch(void* const* d_in, const int* in_sizes, int n_in,
                              void* d_out, int out_size)
{
    const float* feat  = (const float*)d_in[0];
    const float* bbox  = (const float*)d_in[1];
    const float* word  = (const float*)d_in[2];
    const float* sent  = (const float*)d_in[3];
    const float* body  = (const float*)d_in[4];
    const float* W1_o  = (const float*)d_in[5];
    const float* go = (const float*)d_in[6],  *bo = (const float*)d_in[7];
    const float* mo = (const float*)d_in[8],  *vo = (const float*)d_in[9];
    const float* W2_o  = (const float*)d_in[10];
    const float* W1_s  = (const float*)d_in[11];
    const float* gs = (const float*)d_in[12], *bs = (const float*)d_in[13];
    const float* ms = (const float*)d_in[14], *vs = (const float*)d_in[15];
    const float* W2_s  = (const float*)d_in[16];
    const float* W1_b  = (const float*)d_in[17];
    const float* gb = (const float*)d_in[18], *bb = (const float*)d_in[19];
    const float* mb = (const float*)d_in[20], *vb = (const float*)d_in[21];
    const float* W2_b  = (const float*)d_in[22];
    const float* Wc1   = (const float*)d_in[23];
    const float* Wc2   = (const float*)d_in[24];
    const float* Wsa   = (const float*)d_in[25];
    const float* Wf    = (const float*)d_in[26];
    const float* bias_f= (const float*)d_in[27];
    const float* gf = (const float*)d_in[28], *bfv = (const float*)d_in[29];
    const float* mf = (const float*)d_in[30], *vf = (const float*)d_in[31];

    float *xs, *bnf_s, *bnf_t;
    cudaGetSymbolAddress((void**)&xs, g_xs);
    cudaGetSymbolAddress((void**)&bnf_s, g_bnf_s);
    cudaGetSymbolAddress((void**)&bnf_t, g_bnf_t);

    const int SMF = 8 * (128 * 72 * 2);   // 147456 B
    const int SMB = 8 * (128 * 72 * 2);   // 147456 B
    cudaFuncSetAttribute(gemm1_all, cudaFuncAttributeMaxDynamicSharedMemorySize, SMF);
    cudaFuncSetAttribute(gemm2_all, cudaFuncAttributeMaxDynamicSharedMemorySize, SMB);

    prep_bn_kernel<<<1, 512>>>(gs, bs, ms, vs, go, bo, mo, vo,
                               gb, bb, mb, vb, gf, bfv, mf, vf, bias_f);

    split_all<<<2800, 256>>>((const float4*)W1_s, (const float4*)W2_s,
                             (const float4*)W1_o, (const float4*)W2_o,
                             (const float4*)W1_b, (const float4*)W2_b);

    gemm1_all<<<416, 512, SMF>>>(sent, feat, body);
    gemm2_all<<<168, 256, SMB>>>();

    attention_kernel<<<1024, 320>>>(bbox, word, Wc1, Wc2, Wsa);

    // fc: [1024,688] @ [688,256] + bias + BN + relu — 128 CTAs
    sgemm_kernel<32, 64, 16, 4, 4><<<dim3(256 / 64, 1024 / 32), 128>>>(
        1024, 256, 688, xs, Wf, (float*)d_out, 256, bnf_s, bnf_t);
}

// round 14
// speedup vs baseline: 1.1563x; 1.1563x over previous
#include <cuda_runtime.h>
#include <cuda_bf16.h>
#include <mma.h>
#include <math.h>
#include <stdint.h>

using namespace nvcuda;

#define BN_EPS 1e-5f

// ============================ scratch (device globals) ============================
__device__ __nv_bfloat16 g_w1s_hi[512 * 4096], g_w1s_lo[512 * 4096];
__device__ __nv_bfloat16 g_w2s_hi[128 * 512],  g_w2s_lo[128 * 512];
__device__ __nv_bfloat16 g_w1o_hi[128 * 1024], g_w1o_lo[128 * 1024];
__device__ __nv_bfloat16 g_w2o_hi[128 * 128],  g_w2o_lo[128 * 128];
__device__ __nv_bfloat16 g_w1b_hi[256 * 2048], g_w1b_lo[256 * 2048];
__device__ __nv_bfloat16 g_w2b_hi[128 * 256],  g_w2b_lo[128 * 256];
__device__ __nv_bfloat16 g_hs_hi[10240 * 512], g_hs_lo[10240 * 512];
__device__ __nv_bfloat16 g_ho_hi[10240 * 128], g_ho_lo[10240 * 128];
__device__ __nv_bfloat16 g_hb_hi[1024 * 256],  g_hb_lo[1024 * 256];
__device__ float g_part0[10240 * 512];   // sen1 split-K partials
__device__ float g_part1[10240 * 512];
__device__ float g_obj[10240 * 128];
__device__ float g_sen[10240 * 128];
__device__ float g_bod[1024 * 128];
__device__ float g_xs[1024 * 688];
__device__ float g_bns_s[512], g_bns_t[512];
__device__ float g_bno_s[128], g_bno_t[128];
__device__ float g_bnb_s[256], g_bnb_t[256];
__device__ float g_bnf_s[256], g_bnf_t[256];

// ============================ helpers ============================
__device__ __forceinline__ void cp_async16(uint32_t saddr, const void* gptr) {
    asm volatile("cp.async.cg.shared.global [%0], [%1], 16;" :: "r"(saddr), "l"(gptr));
}
__device__ __forceinline__ uint32_t smem_u32(const void* p) {
    uint32_t a;
    asm("{ .reg .u64 t; cvta.to.shared.u64 t, %1; cvt.u32.u64 %0, t; }" : "=r"(a) : "l"(p));
    return a;
}
__device__ __forceinline__ void cp_commit() {
    asm volatile("cp.async.commit_group;" ::: "memory");
}
template<int N>
__device__ __forceinline__ void cp_wait() {
    asm volatile("cp.async.wait_group %0;" :: "n"(N) : "memory");
}

// ============================ BN fold prep ============================
__global__ void prep_bn_kernel(
    const float* __restrict__ gs, const float* __restrict__ bs,
    const float* __restrict__ ms, const float* __restrict__ vs,
    const float* __restrict__ go, const float* __restrict__ bo,
    const float* __restrict__ mo, const float* __restrict__ vo,
    const float* __restrict__ gb, const float* __restrict__ bb,
    const float* __restrict__ mb, const float* __restrict__ vb,
    const float* __restrict__ gf, const float* __restrict__ bfv,
    const float* __restrict__ mf, const float* __restrict__ vf,
    const float* __restrict__ bias_f)
{
    int i = threadIdx.x;
    if (i < 512) { float s = gs[i] * rsqrtf(vs[i] + BN_EPS); g_bns_s[i] = s; g_bns_t[i] = bs[i] - ms[i] * s; }
    if (i < 128) { float s = go[i] * rsqrtf(vo[i] + BN_EPS); g_bno_s[i] = s; g_bno_t[i] = bo[i] - mo[i] * s; }
    if (i < 256) { float s = gb[i] * rsqrtf(vb[i] + BN_EPS); g_bnb_s[i] = s; g_bnb_t[i] = bb[i] - mb[i] * s; }
    if (i < 256) { float s = gf[i] * rsqrtf(vf[i] + BN_EPS); g_bnf_s[i] = s; g_bnf_t[i] = (bias_f[i] - mf[i]) * s + bfv[i]; }
}

// ============================ all weight splits in one launch ============================
__global__ void split_all(
    const float4* __restrict__ W1s, const float4* __restrict__ W2s,
    const float4* __restrict__ W1o, const float4* __restrict__ W2o,
    const float4* __restrict__ W1b, const float4* __restrict__ W2b)
{
    int i = blockIdx.x * blockDim.x + threadIdx.x;
    const float4* src; uint2* hi; uint2* lo; int j;
    if (i < 524288)      { src = W1s; hi = (uint2*)g_w1s_hi; lo = (uint2*)g_w1s_lo; j = i; }
    else if (i < 540672) { src = W2s; hi = (uint2*)g_w2s_hi; lo = (uint2*)g_w2s_lo; j = i - 524288; }
    else if (i < 573440) { src = W1o; hi = (uint2*)g_w1o_hi; lo = (uint2*)g_w1o_lo; j = i - 540672; }
    else if (i < 577536) { src = W2o; hi = (uint2*)g_w2o_hi; lo = (uint2*)g_w2o_lo; j = i - 573440; }
    else if (i < 708608) { src = W1b; hi = (uint2*)g_w1b_hi; lo = (uint2*)g_w1b_lo; j = i - 577536; }
    else if (i < 716800) { src = W2b; hi = (uint2*)g_w2b_hi; lo = (uint2*)g_w2b_lo; j = i - 708608; }
    else return;
    float4 v = src[j];
    union { __nv_bfloat16 h[4]; uint2 u; } H, L;
    H.h[0] = __float2bfloat16(v.x); L.h[0] = __float2bfloat16(v.x - __bfloat162float(H.h[0]));
    H.h[1] = __float2bfloat16(v.y); L.h[1] = __float2bfloat16(v.y - __bfloat162float(H.h[1]));
    H.h[2] = __float2bfloat16(v.z); L.h[2] = __float2bfloat16(v.z - __bfloat162float(H.h[2]));
    H.h[3] = __float2bfloat16(v.w); L.h[3] = __float2bfloat16(v.w - __bfloat162float(H.h[3]));
    hi[j] = H.u; lo[j] = L.u;
}

// ============================ fused-split bf16x3 GEMM core (R9/R12 structure + lda/ldb) ============================
// Single barrier per K-chunk; A planes double-buffered; stsA overlaps mma.
// SMEM: Ahi0|Alo0|Ahi1|Alo1|Bhi0|Blo0|Bhi1|Blo1 = 8 * 18432 = 147456 B.
template<int K, bool BN_RELU>
__device__ __forceinline__ void fgemm_dev(
    int N_TOT, int bm0, int bn0,
    const float* __restrict__ A32, int lda,
    const __nv_bfloat16* __restrict__ Bhi, const __nv_bfloat16* __restrict__ Blo, int ldb,
    float* __restrict__ Cf,
    __nv_bfloat16* __restrict__ Chi, __nv_bfloat16* __restrict__ Clo,
    const float* __restrict__ sc, const float* __restrict__ sh,
    char* smraw)
{
    constexpr int KITERS = K / 64;
    constexpr int LDT = 72;
    constexpr int PL = 128 * LDT * 2;     // 18432 B per plane
    const uint32_t sbase = smem_u32(smraw);

    const int tid = threadIdx.x;
    const int wid = tid >> 5;
    const int lane = tid & 31;
    const int warp_m = wid & 3;
    const int warp_n = wid >> 2;

    wmma::fragment<wmma::accumulator, 16, 16, 16, float> c[2][4];
#pragma unroll
    for (int mi = 0; mi < 2; mi++)
#pragma unroll
        for (int ni = 0; ni < 4; ni++) wmma::fill_fragment(c[mi][ni], 0.0f);

    const int lr = tid >> 3;
    const int lq = tid & 7;

    float4 areg[8];

    auto ldgA = [&](int cix) {
#pragma unroll
        for (int i = 0; i < 4; i++) {
            const float* p = A32 + (size_t)(bm0 + lr + i * 32) * lda + cix * 64 + lq * 8;
            areg[i * 2]     = *reinterpret_cast<const float4*>(p);
            areg[i * 2 + 1] = *reinterpret_cast<const float4*>(p + 4);
        }
    };
    auto cpB = [&](int cix, int s) {
        const uint32_t bh = sbase + 4 * PL + s * 2 * PL;
        const uint32_t bl = bh + PL;
#pragma unroll
        for (int i = 0; i < 4; i++) {
            int r = lr + i * 32;
            cp_async16(bh + r * (LDT * 2) + lq * 16, Bhi + (size_t)(bn0 + r) * ldb + cix * 64 + lq * 8);
            cp_async16(bl + r * (LDT * 2) + lq * 16, Blo + (size_t)(bn0 + r) * ldb + cix * 64 + lq * 8);
        }
        cp_commit();
    };
    auto stsA = [&](int s) {
        char* ah = smraw + s * 2 * PL;
        char* al = ah + PL;
#pragma unroll
        for (int i = 0; i < 4; i++) {
            int r = lr + i * 32;
            float f[8] = { areg[i*2].x, areg[i*2].y, areg[i*2].z, areg[i*2].w,
                           areg[i*2+1].x, areg[i*2+1].y, areg[i*2+1].z, areg[i*2+1].w };
            union { __nv_bfloat16 h[8]; uint4 u; } H, L;
#pragma unroll
            for (int j = 0; j < 8; j++) {
                H.h[j] = __float2bfloat16(f[j]);
                L.h[j] = __float2bfloat16(f[j] - __bfloat162float(H.h[j]));
            }
            *reinterpret_cast<uint4*>(ah + r * (LDT * 2) + lq * 16) = H.u;
            *reinterpret_cast<uint4*>(al + r * (LDT * 2) + lq * 16) = L.u;
        }
    };

    ldgA(0);
    cpB(0, 0);
    stsA(0);
    if (KITERS > 1) ldgA(1);

    for (int cix = 0; cix < KITERS; ++cix) {
        const int s = cix & 1;
        cp_wait<0>();
        __syncthreads();
        if (cix + 1 < KITERS) cpB(cix + 1, s ^ 1);

        const __nv_bfloat16* ah = reinterpret_cast<const __nv_bfloat16*>(smraw + s * 2 * PL);
        const __nv_bfloat16* al = ah + PL / 2;
        const __nv_bfloat16* bh = reinterpret_cast<const __nv_bfloat16*>(smraw + 4 * PL + s * 2 * PL);
        const __nv_bfloat16* bl = bh + PL / 2;
#pragma unroll
        for (int kk = 0; kk < 4; kk++) {
            wmma::fragment<wmma::matrix_a, 16, 16, 16, __nv_bfloat16, wmma::row_major> a_hi[2], a_lo[2];
            wmma::fragment<wmma::matrix_b, 16, 16, 16, __nv_bfloat16, wmma::col_major> b_hi[4], b_lo[4];
#pragma unroll
            for (int mi = 0; mi < 2; mi++) {
                wmma::load_matrix_sync(a_hi[mi], ah + (warp_m * 32 + mi * 16) * LDT + kk * 16, LDT);
                wmma::load_matrix_sync(a_lo[mi], al + (warp_m * 32 + mi * 16) * LDT + kk * 16, LDT);
            }
#pragma unroll
            for (int ni = 0; ni < 4; ni++) {
                wmma::load_matrix_sync(b_hi[ni], bh + (warp_n * 64 + ni * 16) * LDT + kk * 16, LDT);
                wmma::load_matrix_sync(b_lo[ni], bl + (warp_n * 64 + ni * 16) * LDT + kk * 16, LDT);
            }
#pragma unroll
            for (int mi = 0; mi < 2; mi++)
#pragma unroll
                for (int ni = 0; ni < 4; ni++) {
                    wmma::mma_sync(c[mi][ni], a_hi[mi], b_hi[ni], c[mi][ni]);
                    wmma::mma_sync(c[mi][ni], a_lo[mi], b_hi[ni], c[mi][ni]);
                    wmma::mma_sync(c[mi][ni], a_hi[mi], b_lo[ni], c[mi][ni]);
                }
        }
        if (cix + 1 < KITERS) {
            stsA(s ^ 1);
            if (cix + 2 < KITERS) ldgA(cix + 2);
        }
    }
    __syncthreads();

    float* scr = reinterpret_cast<float*>(smraw) + wid * (32 * 68);
#pragma unroll
    for (int mi = 0; mi < 2; mi++)
#pragma unroll
        for (int ni = 0; ni < 4; ni++)
            wmma::store_matrix_sync(scr + mi * 16 * 68 + ni * 16, c[mi][ni], 68, wmma::mem_row_major);
    __syncwarp();

#pragma unroll
    for (int cc = 0; cc < 2; cc++) {
        const int col = bn0 + warp_n * 64 + cc * 32 + lane;
#pragma unroll
        for (int rr = 0; rr < 32; rr++) {
            const size_t row = (size_t)(bm0 + warp_m * 32 + rr);
            float v = scr[rr * 68 + cc * 32 + lane];
            if (BN_RELU) {
                v = fmaxf(fmaf(v, sc[col], sh[col]), 0.f);
                __nv_bfloat16 h = __float2bfloat16(v);
                Chi[row * N_TOT + col] = h;
                Clo[row * N_TOT + col] = __float2bfloat16(v - __bfloat162float(h));
            } else {
                Cf[row * N_TOT + col] = v;
            }
        }
    }
}

// GEMM1 mega-kernel with sen1 split-K2:
// b in [0,640): sen split tiles (K=2048 each, fp32 partials)
// b in [640,656): body1 (K=2048), b in [656,736): obj1 (K=1024)
__global__ __launch_bounds__(256)
void gemm1_all(const float* __restrict__ sent, const float* __restrict__ feat,
               const float* __restrict__ body)
{
    extern __shared__ __align__(16) char smraw[];
    const int b = blockIdx.x;
    if (b < 640) {
        const int k = b & 1, t = b >> 1;
        fgemm_dev<2048, false>(512, (t >> 2) * 128, (t & 3) * 128,
                               sent + k * 2048, 4096,
                               g_w1s_hi + k * 2048, g_w1s_lo + k * 2048, 4096,
                               k ? g_part1 : g_part0, nullptr, nullptr,
                               nullptr, nullptr, smraw);
    } else if (b < 656) {
        const int bb = b - 640;
        fgemm_dev<2048, true>(256, (bb >> 1) * 128, (bb & 1) * 128,
                              body, 2048, g_w1b_hi, g_w1b_lo, 2048,
                              nullptr, g_hb_hi, g_hb_lo, g_bnb_s, g_bnb_t, smraw);
    } else {
        fgemm_dev<1024, true>(128, (b - 656) * 128, 0,
                              feat, 1024, g_w1o_hi, g_w1o_lo, 1024,
                              nullptr, g_ho_hi, g_ho_lo, g_bno_s, g_bno_t, smraw);
    }
}

// sen1 split-K reduction: h = relu((p0+p1)*sc+sh) -> bf16 hi/lo
__global__ void reduce_sen()
{
    int i = blockIdx.x * blockDim.x + threadIdx.x;   // float4 index over 10240*512
    if (i >= 10240 * 512 / 4) return;
    float4 p0 = reinterpret_cast<const float4*>(g_part0)[i];
    float4 p1 = reinterpret_cast<const float4*>(g_part1)[i];
    int col = (i * 4) & 511;
    float v[4] = { p0.x + p1.x, p0.y + p1.y, p0.z + p1.z, p0.w + p1.w };
    union { __nv_bfloat16 h[4]; uint2 u; } H, L;
#pragma unroll
    for (int j = 0; j < 4; j++) {
        float x = fmaxf(fmaf(v[j], g_bns_s[col + j], g_bns_t[col + j]), 0.f);
        H.h[j] = __float2bfloat16(x);
        L.h[j] = __float2bfloat16(x - __bfloat162float(H.h[j]));
    }
    reinterpret_cast<uint2*>(g_hs_hi)[i] = H.u;
    reinterpret_cast<uint2*>(g_hs_lo)[i] = L.u;
}

// ============================ GEMM2: K-major 3-term, 4-plane chunks, double-buffered ============================
template<int K>
__device__ __forceinline__ void wmma_dev(
    int N_TOT, int bm0,
    const __nv_bfloat16* __restrict__ Ahi, const __nv_bfloat16* __restrict__ Alo,
    const __nv_bfloat16* __restrict__ Bhi, const __nv_bfloat16* __restrict__ Blo,
    float* __restrict__ Cf, char* smraw)
{
    constexpr int KITERS = K / 64;
    constexpr int LDT = 72;
    constexpr int PL = 128 * LDT * 2;      // 18432 B
    constexpr int STG = 4 * PL;
    const uint32_t sbase = smem_u32(smraw);

    const int tid = threadIdx.x;
    const int wid = tid >> 5;
    const int lane = tid & 31;
    const int warp_m = wid & 3;
    const int warp_n = wid >> 2;

    wmma::fragment<wmma::accumulator, 16, 16, 16, float> c[2][4];
#pragma unroll
    for (int mi = 0; mi < 2; mi++)
#pragma unroll
        for (int ni = 0; ni < 4; ni++) wmma::fill_fragment(c[mi][ni], 0.0f);

    const int lr = tid >> 3;
    const int lq = tid & 7;

    auto load_chunk = [&](int cix, int s) {
        const uint32_t base = sbase + s * STG;
#pragma unroll
        for (int i = 0; i < 4; i++) {
            int r = lr + i * 32;
            uint32_t off = r * (LDT * 2) + lq * 16;
            size_t ga = (size_t)(bm0 + r) * K + cix * 64 + lq * 8;
            size_t gb = (size_t)r * K + cix * 64 + lq * 8;
            cp_async16(base + off,          Ahi + ga);
            cp_async16(base + PL + off,     Alo + ga);
            cp_async16(base + 2 * PL + off, Bhi + gb);
            cp_async16(base + 3 * PL + off, Blo + gb);
        }
        cp_commit();
    };

    load_chunk(0, 0);
    for (int cix = 0; cix < KITERS; ++cix) {
        const int s = cix & 1;
        cp_wait<0>();
        __syncthreads();
        if (cix + 1 < KITERS) load_chunk(cix + 1, s ^ 1);

        const __nv_bfloat16* ah = reinterpret_cast<const __nv_bfloat16*>(smraw + s * STG);
        const __nv_bfloat16* al = ah + PL / 2;
        const __nv_bfloat16* bh = al + PL / 2;
        const __nv_bfloat16* bl = bh + PL / 2;
#pragma unroll
        for (int kk = 0; kk < 4; kk++) {
            wmma::fragment<wmma::matrix_a, 16, 16, 16, __nv_bfloat16, wmma::row_major> a_hi[2], a_lo[2];
            wmma::fragment<wmma::matrix_b, 16, 16, 16, __nv_bfloat16, wmma::col_major> b_hi[4], b_lo[4];
#pragma unroll
            for (int mi = 0; mi < 2; mi++) {
                wmma::load_matrix_sync(a_hi[mi], ah + (warp_m * 32 + mi * 16) * LDT + kk * 16, LDT);
                wmma::load_matrix_sync(a_lo[mi], al + (warp_m * 32 + mi * 16) * LDT + kk * 16, LDT);
            }
#pragma unroll
            for (int ni = 0; ni < 4; ni++) {
                wmma::load_matrix_sync(b_hi[ni], bh + (warp_n * 64 + ni * 16) * LDT + kk * 16, LDT);
                wmma::load_matrix_sync(b_lo[ni], bl + (warp_n * 64 + ni * 16) * LDT + kk * 16, LDT);
            }
#pragma unroll
            for (int mi = 0; mi < 2; mi++)
#pragma unroll
                for (int ni = 0; ni < 4; ni++) {
                    wmma::mma_sync(c[mi][ni], a_hi[mi], b_hi[ni], c[mi][ni]);
                    wmma::mma_sync(c[mi][ni], a_lo[mi], b_hi[ni], c[mi][ni]);
                    wmma::mma_sync(c[mi][ni], a_hi[mi], b_lo[ni], c[mi][ni]);
                }
        }
    }
    __syncthreads();

    float* scr = reinterpret_cast<float*>(smraw) + wid * (32 * 68);
#pragma unroll
    for (int mi = 0; mi < 2; mi++)
#pragma unroll
        for (int ni = 0; ni < 4; ni++)
            wmma::store_matrix_sync(scr + mi * 16 * 68 + ni * 16, c[mi][ni], 68, wmma::mem_row_major);
    __syncwarp();

#pragma unroll
    for (int cc = 0; cc < 2; cc++) {
        const int col = warp_n * 64 + cc * 32 + lane;
#pragma unroll
        for (int rr = 0; rr < 32; rr++) {
            const size_t row = (size_t)(bm0 + warp_m * 32 + rr);
            Cf[row * N_TOT + col] = scr[rr * 68 + cc * 32 + lane];
        }
    }
}

// GEMM2 mega-kernel: sen2 (80) + obj2 (80) + body2 (8) = 168 CTAs
__global__ __launch_bounds__(256)
void gemm2_all()
{
    extern __shared__ __align__(16) char smraw[];
    const int b = blockIdx.x;
    if (b < 80) {
        wmma_dev<512>(128, b * 128, g_hs_hi, g_hs_lo, g_w2s_hi, g_w2s_lo, g_sen, smraw);
    } else if (b < 160) {
        wmma_dev<128>(128, (b - 80) * 128, g_ho_hi, g_ho_lo, g_w2o_hi, g_w2o_lo, g_obj, smraw);
    } else {
        wmma_dev<256>(128, (b - 160) * 128, g_hb_hi, g_hb_lo, g_w2b_hi, g_w2b_lo, g_bod, smraw);
    }
}

// ============================ fp32 SGEMM (fc, K=688) ============================
template<int BM, int BN, int BK, int TM, int TN>
__global__ void sgemm_kernel(int M, int N, int K,
    const float* __restrict__ A, const float* __restrict__ B,
    float* __restrict__ C, int ldc,
    const float* __restrict__ sc, const float* __restrict__ sh)
{
    constexpr int THREADS = (BM / TM) * (BN / TN);
    __shared__ float As[BK][BM];
    __shared__ float Bs[BK][BN];
    const int tid = threadIdx.x;
    const int bn0 = blockIdx.x * BN;
    const int bm0 = blockIdx.y * BM;
    const int tx = tid % (BN / TN);
    const int ty = tid / (BN / TN);

    float acc[TM][TN];
#pragma unroll
    for (int i = 0; i < TM; i++)
#pragma unroll
        for (int j = 0; j < TN; j++) acc[i][j] = 0.f;

    constexpr int AV = BM * BK / 4 / THREADS;
    constexpr int BV = BN * BK / 4 / THREADS;

    for (int k0 = 0; k0 < K; k0 += BK) {
#pragma unroll
        for (int i = 0; i < AV; i++) {
            int idx = tid + i * THREADS;
            int r = idx / (BK / 4), c4 = idx % (BK / 4);
            float4 v = *reinterpret_cast<const float4*>(A + (size_t)(bm0 + r) * K + k0 + c4 * 4);
            As[c4 * 4 + 0][r] = v.x; As[c4 * 4 + 1][r] = v.y;
            As[c4 * 4 + 2][r] = v.z; As[c4 * 4 + 3][r] = v.w;
        }
#pragma unroll
        for (int i = 0; i < BV; i++) {
            int idx = tid + i * THREADS;
            int r = idx / (BK / 4), c4 = idx % (BK / 4);
            float4 v = *reinterpret_cast<const float4*>(B + (size_t)(bn0 + r) * K + k0 + c4 * 4);
            Bs[c4 * 4 + 0][r] = v.x; Bs[c4 * 4 + 1][r] = v.y;
            Bs[c4 * 4 + 2][r] = v.z; Bs[c4 * 4 + 3][r] = v.w;
        }
        __syncthreads();
#pragma unroll
        for (int kk = 0; kk < BK; kk++) {
            float a[TM], b[TN];
#pragma unroll
            for (int i = 0; i < TM; i += 4) {
                float4 v = *reinterpret_cast<const float4*>(&As[kk][ty * TM + i]);
                a[i] = v.x; a[i + 1] = v.y; a[i + 2] = v.z; a[i + 3] = v.w;
            }
#pragma unroll
            for (int j = 0; j < TN; j += 4) {
                float4 v = *reinterpret_cast<const float4*>(&Bs[kk][tx * TN + j]);
                b[j] = v.x; b[j + 1] = v.y; b[j + 2] = v.z; b[j + 3] = v.w;
            }
#pragma unroll
            for (int i = 0; i < TM; i++)
#pragma unroll
                for (int j = 0; j < TN; j++)
                    acc[i][j] = fmaf(a[i], b[j], acc[i][j]);
        }
        __syncthreads();
    }
#pragma unroll
    for (int i = 0; i < TM; i++) {
        int row = bm0 + ty * TM + i;
#pragma unroll
        for (int j = 0; j < TN; j++) {
            int col = bn0 + tx * TN + j;
            float v = acc[i][j];
            if (sc) v = fmaxf(fmaf(v, sc[col], sh[col]), 0.f);
            C[(size_t)row * ldc + col] = v;
        }
    }
}

// ============================ fused attention stage ============================
__global__ void attention_kernel(
    const float* __restrict__ bbox, const float* __restrict__ word,
    const float* __restrict__ Wc1, const float* __restrict__ Wc2,
    const float* __restrict__ Wsa)
{
    __shared__ float xt[10][688];
    __shared__ float rmean[10], rmax[10], att[10];
    __shared__ float csum[688], cmax[688];

    const int b = blockIdx.x;
    const int tid = threadIdx.x;

    for (int idx = tid; idx < 10 * 688; idx += blockDim.x) {
        int n = idx / 688, f = idx % 688;
        int rn = b * 10 + n;
        float v;
        if (f < 128)       v = g_obj[rn * 128 + f];
        else if (f < 132)  v = bbox[rn * 4 + (f - 128)];
        else if (f < 432)  v = word[rn * 300 + (f - 132)];
        else if (f < 560)  v = g_sen[rn * 128 + (f - 432)];
        else               v = g_bod[b * 128 + (f - 560)];
        xt[n][f] = v;
    }
    __syncthreads();

    int w = tid / 32, lane = tid % 32;
    if (w < 10) {
        float s = 0.f, mx = -3.402823e38f;
        for (int f = lane; f < 688; f += 32) {
            float v = xt[w][f];
            s += v; mx = fmaxf(mx, v);
        }
#pragma unroll
        for (int o = 16; o; o >>= 1) {
            s += __shfl_down_sync(0xffffffff, s, o);
            mx = fmaxf(mx, __shfl_down_sync(0xffffffff, mx, o));
        }
        if (lane == 0) { rmean[w] = s * (1.f / 688.f); rmax[w] = mx; }
    }
    __syncthreads();

    if (tid == 0) {
        float h[5], o1[10], o2[10];
        for (int j = 0; j < 5; j++) {
            float s = 0.f;
            for (int i = 0; i < 10; i++) s += rmean[i] * Wc1[j * 10 + i];
            h[j] = fmaxf(s, 0.f);
        }
        for (int n = 0; n < 10; n++) {
            float s = 0.f;
            for (int j = 0; j < 5; j++) s += h[j] * Wc2[n * 5 + j];
            o1[n] = s;
        }
        for (int j = 0; j < 5; j++) {
            float s = 0.f;
            for (int i = 0; i < 10; i++) s += rmax[i] * Wc1[j * 10 + i];
            h[j] = fmaxf(s, 0.f);
        }
        for (int n = 0; n < 10; n++) {
            float s = 0.f;
            for (int j = 0; j < 5; j++) s += h[j] * Wc2[n * 5 + j];
            o2[n] = s;
        }
        for (int n = 0; n < 10; n++)
            att[n] = 1.f / (1.f + expf(-(o1[n] + o2[n])));
    }
    __syncthreads();

    for (int f = tid; f < 688; f += blockDim.x) {
        float s = 0.f, mx = -3.402823e38f;
#pragma unroll
        for (int n = 0; n < 10; n++) {
            float v = xt[n][f] * att[n];
            s += v; mx = fmaxf(mx, v);
        }
        csum[f] = s; cmax[f] = mx;
    }
    __syncthreads();

    for (int f = tid; f < 688; f += blockDim.x) {
        float sa = 0.f;
#pragma unroll
        for (int j = 0; j < 7; j++) {
            int p = f + j - 3;
            if (p >= 0 && p < 688)
                sa += Wsa[j] * (csum[p] * 0.1f) + Wsa[7 + j] * cmax[p];
        }
        float sig = 1.f / (1.f + expf(-sa));
        g_xs[b * 688 + f] = csum[f] * sig;
    }
}

// ============================ launch ============================
extern "C" void kernel_launch(void* const* d_in, const int* in_sizes, int n_in,
                              void* d_out, int out_size)
{
    const float* feat  = (const float*)d_in[0];
    const float* bbox  = (const float*)d_in[1];
    const float* word  = (const float*)d_in[2];
    const float* sent  = (const float*)d_in[3];
    const float* body  = (const float*)d_in[4];
    const float* W1_o  = (const float*)d_in[5];
    const float* go = (const float*)d_in[6],  *bo = (const float*)d_in[7];
    const float* mo = (const float*)d_in[8],  *vo = (const float*)d_in[9];
    const float* W2_o  = (const float*)d_in[10];
    const float* W1_s  = (const float*)d_in[11];
    const float* gs = (const float*)d_in[12], *bs = (const float*)d_in[13];
    const float* ms = (const float*)d_in[14], *vs = (const float*)d_in[15];
    const float* W2_s  = (const float*)d_in[16];
    const float* W1_b  = (const float*)d_in[17];
    const float* gb = (const float*)d_in[18], *bb = (const float*)d_in[19];
    const float* mb = (const float*)d_in[20], *vb = (const float*)d_in[21];
    const float* W2_b  = (const float*)d_in[22];
    const float* Wc1   = (const float*)d_in[23];
    const float* Wc2   = (const float*)d_in[24];
    const float* Wsa   = (const float*)d_in[25];
    const float* Wf    = (const float*)d_in[26];
    const float* bias_f= (const float*)d_in[27];
    const float* gf = (const float*)d_in[28], *bfv = (const float*)d_in[29];
    const float* mf = (const float*)d_in[30], *vf = (const float*)d_in[31];

    float *xs, *bnf_s, *bnf_t;
    cudaGetSymbolAddress((void**)&xs, g_xs);
    cudaGetSymbolAddress((void**)&bnf_s, g_bnf_s);
    cudaGetSymbolAddress((void**)&bnf_t, g_bnf_t);

    const int SMF = 8 * (128 * 72 * 2);   // 147456 B
    const int SMB = 8 * (128 * 72 * 2);   // 147456 B
    cudaFuncSetAttribute(gemm1_all, cudaFuncAttributeMaxDynamicSharedMemorySize, SMF);
    cudaFuncSetAttribute(gemm2_all, cudaFuncAttributeMaxDynamicSharedMemorySize, SMB);

    prep_bn_kernel<<<1, 512>>>(gs, bs, ms, vs, go, bo, mo, vo,
                               gb, bb, mb, vb, gf, bfv, mf, vf, bias_f);

    split_all<<<2800, 256>>>((const float4*)W1_s, (const float4*)W2_s,
                             (const float4*)W1_o, (const float4*)W2_o,
                             (const float4*)W1_b, (const float4*)W2_b);

    // gemm1 with sen1 split-K2: 640 sen halves + 16 body + 80 obj = 736 CTAs
    gemm1_all<<<736, 256, SMF>>>(sent, feat, body);
    reduce_sen<<<(10240 * 512 / 4 + 255) / 256, 256>>>();

    gemm2_all<<<168, 256, SMB>>>();

    attention_kernel<<<1024, 320>>>(bbox, word, Wc1, Wc2, Wsa);

    // fc: [1024,688] @ [688,256] + bias + BN + relu — 128 CTAs
    sgemm_kernel<32, 64, 16, 4, 4><<<dim3(256 / 64, 1024 / 32), 128>>>(
        1024, 256, 688, xs, Wf, (float*)d_out, 256, bnf_s, bnf_t);
}

// round 15
// speedup vs baseline: 1.1658x; 1.0082x over previous
#include <cuda_runtime.h>
#include <cuda_bf16.h>
#include <mma.h>
#include <math.h>
#include <stdint.h>

using namespace nvcuda;

#define BN_EPS 1e-5f

// ============================ scratch (device globals) ============================
__device__ __nv_bfloat16 g_w1s_hi[512 * 4096], g_w1s_lo[512 * 4096];
__device__ __nv_bfloat16 g_w2s_hi[128 * 512],  g_w2s_lo[128 * 512];
__device__ __nv_bfloat16 g_w1o_hi[128 * 1024], g_w1o_lo[128 * 1024];
__device__ __nv_bfloat16 g_w2o_hi[128 * 128],  g_w2o_lo[128 * 128];
__device__ __nv_bfloat16 g_w1b_hi[256 * 2048], g_w1b_lo[256 * 2048];
__device__ __nv_bfloat16 g_w2b_hi[128 * 256],  g_w2b_lo[128 * 256];
__device__ __nv_bfloat16 g_hs_hi[10240 * 512], g_hs_lo[10240 * 512];
__device__ __nv_bfloat16 g_ho_hi[10240 * 128], g_ho_lo[10240 * 128];
__device__ __nv_bfloat16 g_hb_hi[1024 * 256],  g_hb_lo[1024 * 256];
__device__ float g_part0[10240 * 512];   // sen1 split-K partials
__device__ float g_part1[10240 * 512];
__device__ float g_obj[10240 * 128];
__device__ float g_sen[10240 * 128];
__device__ float g_bod[1024 * 128];
__device__ float g_xs[1024 * 688];
__device__ float g_bns_s[512], g_bns_t[512];
__device__ float g_bno_s[128], g_bno_t[128];
__device__ float g_bnb_s[256], g_bnb_t[256];
__device__ float g_bnf_s[256], g_bnf_t[256];

// ============================ helpers ============================
__device__ __forceinline__ void cp_async16(uint32_t saddr, const void* gptr) {
    asm volatile("cp.async.cg.shared.global [%0], [%1], 16;" :: "r"(saddr), "l"(gptr));
}
__device__ __forceinline__ uint32_t smem_u32(const void* p) {
    uint32_t a;
    asm("{ .reg .u64 t; cvta.to.shared.u64 t, %1; cvt.u32.u64 %0, t; }" : "=r"(a) : "l"(p));
    return a;
}
__device__ __forceinline__ void cp_commit() {
    asm volatile("cp.async.commit_group;" ::: "memory");
}
template<int N>
__device__ __forceinline__ void cp_wait() {
    asm volatile("cp.async.wait_group %0;" :: "n"(N) : "memory");
}

// ============================ BN fold prep ============================
__global__ void prep_bn_kernel(
    const float* __restrict__ gs, const float* __restrict__ bs,
    const float* __restrict__ ms, const float* __restrict__ vs,
    const float* __restrict__ go, const float* __restrict__ bo,
    const float* __restrict__ mo, const float* __restrict__ vo,
    const float* __restrict__ gb, const float* __restrict__ bb,
    const float* __restrict__ mb, const float* __restrict__ vb,
    const float* __restrict__ gf, const float* __restrict__ bfv,
    const float* __restrict__ mf, const float* __restrict__ vf,
    const float* __restrict__ bias_f)
{
    int i = threadIdx.x;
    if (i < 512) { float s = gs[i] * rsqrtf(vs[i] + BN_EPS); g_bns_s[i] = s; g_bns_t[i] = bs[i] - ms[i] * s; }
    if (i < 128) { float s = go[i] * rsqrtf(vo[i] + BN_EPS); g_bno_s[i] = s; g_bno_t[i] = bo[i] - mo[i] * s; }
    if (i < 256) { float s = gb[i] * rsqrtf(vb[i] + BN_EPS); g_bnb_s[i] = s; g_bnb_t[i] = bb[i] - mb[i] * s; }
    if (i < 256) { float s = gf[i] * rsqrtf(vf[i] + BN_EPS); g_bnf_s[i] = s; g_bnf_t[i] = (bias_f[i] - mf[i]) * s + bfv[i]; }
}

// ============================ all weight splits in one launch ============================
__global__ void split_all(
    const float4* __restrict__ W1s, const float4* __restrict__ W2s,
    const float4* __restrict__ W1o, const float4* __restrict__ W2o,
    const float4* __restrict__ W1b, const float4* __restrict__ W2b)
{
    int i = blockIdx.x * blockDim.x + threadIdx.x;
    const float4* src; uint2* hi; uint2* lo; int j;
    if (i < 524288)      { src = W1s; hi = (uint2*)g_w1s_hi; lo = (uint2*)g_w1s_lo; j = i; }
    else if (i < 540672) { src = W2s; hi = (uint2*)g_w2s_hi; lo = (uint2*)g_w2s_lo; j = i - 524288; }
    else if (i < 573440) { src = W1o; hi = (uint2*)g_w1o_hi; lo = (uint2*)g_w1o_lo; j = i - 540672; }
    else if (i < 577536) { src = W2o; hi = (uint2*)g_w2o_hi; lo = (uint2*)g_w2o_lo; j = i - 573440; }
    else if (i < 708608) { src = W1b; hi = (uint2*)g_w1b_hi; lo = (uint2*)g_w1b_lo; j = i - 577536; }
    else if (i < 716800) { src = W2b; hi = (uint2*)g_w2b_hi; lo = (uint2*)g_w2b_lo; j = i - 708608; }
    else return;
    float4 v = src[j];
    union { __nv_bfloat16 h[4]; uint2 u; } H, L;
    H.h[0] = __float2bfloat16(v.x); L.h[0] = __float2bfloat16(v.x - __bfloat162float(H.h[0]));
    H.h[1] = __float2bfloat16(v.y); L.h[1] = __float2bfloat16(v.y - __bfloat162float(H.h[1]));
    H.h[2] = __float2bfloat16(v.z); L.h[2] = __float2bfloat16(v.z - __bfloat162float(H.h[2]));
    H.h[3] = __float2bfloat16(v.w); L.h[3] = __float2bfloat16(v.w - __bfloat162float(H.h[3]));
    hi[j] = H.u; lo[j] = L.u;
}

// ============================ fused-split bf16x3 GEMM core (64x128 tile, 2 CTAs/SM) ============================
// R9 pipeline preserved: A planes double-buffered, 1 barrier/chunk, stsA overlaps mma.
// SMEM: Ahi0|Alo0|Ahi1|Alo1 (4x9216) | Bhi0|Blo0|Bhi1|Blo1 (4x18432) = 110592 B -> 2 CTAs/SM.
// 8 warps as 2x4 (warp tile 32x32).
template<int K, bool BN_RELU>
__device__ __forceinline__ void fgemm_dev(
    int N_TOT, int bm0, int bn0,
    const float* __restrict__ A32, int lda,
    const __nv_bfloat16* __restrict__ Bhi, const __nv_bfloat16* __restrict__ Blo, int ldb,
    float* __restrict__ Cf,
    __nv_bfloat16* __restrict__ Chi, __nv_bfloat16* __restrict__ Clo,
    const float* __restrict__ sc, const float* __restrict__ sh,
    char* smraw)
{
    constexpr int KITERS = K / 64;
    constexpr int LDT = 72;
    constexpr int APL = 64 * LDT * 2;      // 9216 B
    constexpr int BPL = 128 * LDT * 2;     // 18432 B
    const uint32_t sbase = smem_u32(smraw);

    const int tid = threadIdx.x;
    const int wid = tid >> 5;
    const int lane = tid & 31;
    const int warp_m = wid & 1;            // 2 slabs of 32 rows
    const int warp_n = wid >> 1;           // 4 slabs of 32 cols

    wmma::fragment<wmma::accumulator, 16, 16, 16, float> c[2][2];
#pragma unroll
    for (int mi = 0; mi < 2; mi++)
#pragma unroll
        for (int ni = 0; ni < 2; ni++) wmma::fill_fragment(c[mi][ni], 0.0f);

    const int lr = tid >> 3;               // 0..31
    const int lq = tid & 7;

    float4 areg[4];                        // 2 rows x 8 floats

    auto ldgA = [&](int cix) {
#pragma unroll
        for (int i = 0; i < 2; i++) {
            const float* p = A32 + (size_t)(bm0 + lr + i * 32) * lda + cix * 64 + lq * 8;
            areg[i * 2]     = *reinterpret_cast<const float4*>(p);
            areg[i * 2 + 1] = *reinterpret_cast<const float4*>(p + 4);
        }
    };
    auto cpB = [&](int cix, int s) {
        const uint32_t bh = sbase + 4 * APL + s * 2 * BPL;
        const uint32_t bl = bh + BPL;
#pragma unroll
        for (int i = 0; i < 4; i++) {
            int r = lr + i * 32;
            cp_async16(bh + r * (LDT * 2) + lq * 16, Bhi + (size_t)(bn0 + r) * ldb + cix * 64 + lq * 8);
            cp_async16(bl + r * (LDT * 2) + lq * 16, Blo + (size_t)(bn0 + r) * ldb + cix * 64 + lq * 8);
        }
        cp_commit();
    };
    auto stsA = [&](int s) {
        char* ah = smraw + s * 2 * APL;
        char* al = ah + APL;
#pragma unroll
        for (int i = 0; i < 2; i++) {
            int r = lr + i * 32;
            float f[8] = { areg[i*2].x, areg[i*2].y, areg[i*2].z, areg[i*2].w,
                           areg[i*2+1].x, areg[i*2+1].y, areg[i*2+1].z, areg[i*2+1].w };
            union { __nv_bfloat16 h[8]; uint4 u; } H, L;
#pragma unroll
            for (int j = 0; j < 8; j++) {
                H.h[j] = __float2bfloat16(f[j]);
                L.h[j] = __float2bfloat16(f[j] - __bfloat162float(H.h[j]));
            }
            *reinterpret_cast<uint4*>(ah + r * (LDT * 2) + lq * 16) = H.u;
            *reinterpret_cast<uint4*>(al + r * (LDT * 2) + lq * 16) = L.u;
        }
    };

    // prologue
    ldgA(0);
    cpB(0, 0);
    stsA(0);
    if (KITERS > 1) ldgA(1);

    for (int cix = 0; cix < KITERS; ++cix) {
        const int s = cix & 1;
        cp_wait<0>();          // B(cix) resident
        __syncthreads();       // all warps: stsA(cix) done, mma(cix-1) done
        if (cix + 1 < KITERS) cpB(cix + 1, s ^ 1);

        const __nv_bfloat16* ah = reinterpret_cast<const __nv_bfloat16*>(smraw + s * 2 * APL);
        const __nv_bfloat16* al = ah + APL / 2;
        const __nv_bfloat16* bh = reinterpret_cast<const __nv_bfloat16*>(smraw + 4 * APL + s * 2 * BPL);
        const __nv_bfloat16* bl = bh + BPL / 2;
#pragma unroll
        for (int kk = 0; kk < 4; kk++) {
            wmma::fragment<wmma::matrix_a, 16, 16, 16, __nv_bfloat16, wmma::row_major> a_hi[2], a_lo[2];
            wmma::fragment<wmma::matrix_b, 16, 16, 16, __nv_bfloat16, wmma::col_major> b_hi[2], b_lo[2];
#pragma unroll
            for (int mi = 0; mi < 2; mi++) {
                wmma::load_matrix_sync(a_hi[mi], ah + (warp_m * 32 + mi * 16) * LDT + kk * 16, LDT);
                wmma::load_matrix_sync(a_lo[mi], al + (warp_m * 32 + mi * 16) * LDT + kk * 16, LDT);
            }
#pragma unroll
            for (int ni = 0; ni < 2; ni++) {
                wmma::load_matrix_sync(b_hi[ni], bh + (warp_n * 32 + ni * 16) * LDT + kk * 16, LDT);
                wmma::load_matrix_sync(b_lo[ni], bl + (warp_n * 32 + ni * 16) * LDT + kk * 16, LDT);
            }
#pragma unroll
            for (int mi = 0; mi < 2; mi++)
#pragma unroll
                for (int ni = 0; ni < 2; ni++) {
                    wmma::mma_sync(c[mi][ni], a_hi[mi], b_hi[ni], c[mi][ni]);
                    wmma::mma_sync(c[mi][ni], a_lo[mi], b_hi[ni], c[mi][ni]);
                    wmma::mma_sync(c[mi][ni], a_hi[mi], b_lo[ni], c[mi][ni]);
                }
        }
        if (cix + 1 < KITERS) {
            stsA(s ^ 1);                       // overlaps other warps' mma
            if (cix + 2 < KITERS) ldgA(cix + 2);
        }
    }
    __syncthreads();

    // epilogue: 8 warps x 32x36 f32 scratch (36864 B)
    float* scr = reinterpret_cast<float*>(smraw) + wid * (32 * 36);
#pragma unroll
    for (int mi = 0; mi < 2; mi++)
#pragma unroll
        for (int ni = 0; ni < 2; ni++)
            wmma::store_matrix_sync(scr + mi * 16 * 36 + ni * 16, c[mi][ni], 36, wmma::mem_row_major);
    __syncwarp();

    const int col = bn0 + warp_n * 32 + lane;
#pragma unroll
    for (int rr = 0; rr < 32; rr++) {
        const size_t row = (size_t)(bm0 + warp_m * 32 + rr);
        float v = scr[rr * 36 + lane];
        if (BN_RELU) {
            v = fmaxf(fmaf(v, sc[col], sh[col]), 0.f);
            __nv_bfloat16 h = __float2bfloat16(v);
            Chi[row * N_TOT + col] = h;
            Clo[row * N_TOT + col] = __float2bfloat16(v - __bfloat162float(h));
        } else {
            Cf[row * N_TOT + col] = v;
        }
    }
}

// GEMM1 mega-kernel (64-row tiles, sen split-K2):
// b in [0,1280): sen halves; [1280,1312): body1; [1312,1472): obj1
__global__ __launch_bounds__(256, 2)
void gemm1_all(const float* __restrict__ sent, const float* __restrict__ feat,
               const float* __restrict__ body)
{
    extern __shared__ __align__(16) char smraw[];
    const int b = blockIdx.x;
    if (b < 1280) {
        const int k = b & 1, t = b >> 1;          // t in [0,640): 160 M-tiles x 4 N
        fgemm_dev<2048, false>(512, (t >> 2) * 64, (t & 3) * 128,
                               sent + k * 2048, 4096,
                               g_w1s_hi + k * 2048, g_w1s_lo + k * 2048, 4096,
                               k ? g_part1 : g_part0, nullptr, nullptr,
                               nullptr, nullptr, smraw);
    } else if (b < 1312) {
        const int bb = b - 1280;                  // 16 M-tiles x 2 N
        fgemm_dev<2048, true>(256, (bb >> 1) * 64, (bb & 1) * 128,
                              body, 2048, g_w1b_hi, g_w1b_lo, 2048,
                              nullptr, g_hb_hi, g_hb_lo, g_bnb_s, g_bnb_t, smraw);
    } else {
        const int bo = b - 1312;                  // 160 M-tiles x 1 N
        fgemm_dev<1024, true>(128, bo * 64, 0,
                              feat, 1024, g_w1o_hi, g_w1o_lo, 1024,
                              nullptr, g_ho_hi, g_ho_lo, g_bno_s, g_bno_t, smraw);
    }
}

// sen1 split-K reduction: h = relu((p0+p1)*sc+sh) -> bf16 hi/lo
__global__ void reduce_sen()
{
    int i = blockIdx.x * blockDim.x + threadIdx.x;
    if (i >= 10240 * 512 / 4) return;
    float4 p0 = reinterpret_cast<const float4*>(g_part0)[i];
    float4 p1 = reinterpret_cast<const float4*>(g_part1)[i];
    int col = (i * 4) & 511;
    float v[4] = { p0.x + p1.x, p0.y + p1.y, p0.z + p1.z, p0.w + p1.w };
    union { __nv_bfloat16 h[4]; uint2 u; } H, L;
#pragma unroll
    for (int j = 0; j < 4; j++) {
        float x = fmaxf(fmaf(v[j], g_bns_s[col + j], g_bns_t[col + j]), 0.f);
        H.h[j] = __float2bfloat16(x);
        L.h[j] = __float2bfloat16(x - __bfloat162float(H.h[j]));
    }
    reinterpret_cast<uint2*>(g_hs_hi)[i] = H.u;
    reinterpret_cast<uint2*>(g_hs_lo)[i] = L.u;
}

// ============================ GEMM2: K-major 3-term, 4-plane chunks, double-buffered ============================
template<int K>
__device__ __forceinline__ void wmma_dev(
    int N_TOT, int bm0,
    const __nv_bfloat16* __restrict__ Ahi, const __nv_bfloat16* __restrict__ Alo,
    const __nv_bfloat16* __restrict__ Bhi, const __nv_bfloat16* __restrict__ Blo,
    float* __restrict__ Cf, char* smraw)
{
    constexpr int KITERS = K / 64;
    constexpr int LDT = 72;
    constexpr int PL = 128 * LDT * 2;      // 18432 B
    constexpr int STG = 4 * PL;
    const uint32_t sbase = smem_u32(smraw);

    const int tid = threadIdx.x;
    const int wid = tid >> 5;
    const int lane = tid & 31;
    const int warp_m = wid & 3;
    const int warp_n = wid >> 2;

    wmma::fragment<wmma::accumulator, 16, 16, 16, float> c[2][4];
#pragma unroll
    for (int mi = 0; mi < 2; mi++)
#pragma unroll
        for (int ni = 0; ni < 4; ni++) wmma::fill_fragment(c[mi][ni], 0.0f);

    const int lr = tid >> 3;
    const int lq = tid & 7;

    auto load_chunk = [&](int cix, int s) {
        const uint32_t base = sbase + s * STG;
#pragma unroll
        for (int i = 0; i < 4; i++) {
            int r = lr + i * 32;
            uint32_t off = r * (LDT * 2) + lq * 16;
            size_t ga = (size_t)(bm0 + r) * K + cix * 64 + lq * 8;
            size_t gb = (size_t)r * K + cix * 64 + lq * 8;
            cp_async16(base + off,          Ahi + ga);
            cp_async16(base + PL + off,     Alo + ga);
            cp_async16(base + 2 * PL + off, Bhi + gb);
            cp_async16(base + 3 * PL + off, Blo + gb);
        }
        cp_commit();
    };

    load_chunk(0, 0);
    for (int cix = 0; cix < KITERS; ++cix) {
        const int s = cix & 1;
        cp_wait<0>();
        __syncthreads();
        if (cix + 1 < KITERS) load_chunk(cix + 1, s ^ 1);

        const __nv_bfloat16* ah = reinterpret_cast<const __nv_bfloat16*>(smraw + s * STG);
        const __nv_bfloat16* al = ah + PL / 2;
        const __nv_bfloat16* bh = al + PL / 2;
        const __nv_bfloat16* bl = bh + PL / 2;
#pragma unroll
        for (int kk = 0; kk < 4; kk++) {
            wmma::fragment<wmma::matrix_a, 16, 16, 16, __nv_bfloat16, wmma::row_major> a_hi[2], a_lo[2];
            wmma::fragment<wmma::matrix_b, 16, 16, 16, __nv_bfloat16, wmma::col_major> b_hi[4], b_lo[4];
#pragma unroll
            for (int mi = 0; mi < 2; mi++) {
                wmma::load_matrix_sync(a_hi[mi], ah + (warp_m * 32 + mi * 16) * LDT + kk * 16, LDT);
                wmma::load_matrix_sync(a_lo[mi], al + (warp_m * 32 + mi * 16) * LDT + kk * 16, LDT);
            }
#pragma unroll
            for (int ni = 0; ni < 4; ni++) {
                wmma::load_matrix_sync(b_hi[ni], bh + (warp_n * 64 + ni * 16) * LDT + kk * 16, LDT);
                wmma::load_matrix_sync(b_lo[ni], bl + (warp_n * 64 + ni * 16) * LDT + kk * 16, LDT);
            }
#pragma unroll
            for (int mi = 0; mi < 2; mi++)
#pragma unroll
                for (int ni = 0; ni < 4; ni++) {
                    wmma::mma_sync(c[mi][ni], a_hi[mi], b_hi[ni], c[mi][ni]);
                    wmma::mma_sync(c[mi][ni], a_lo[mi], b_hi[ni], c[mi][ni]);
                    wmma::mma_sync(c[mi][ni], a_hi[mi], b_lo[ni], c[mi][ni]);
                }
        }
    }
    __syncthreads();

    float* scr = reinterpret_cast<float*>(smraw) + wid * (32 * 68);
#pragma unroll
    for (int mi = 0; mi < 2; mi++)
#pragma unroll
        for (int ni = 0; ni < 4; ni++)
            wmma::store_matrix_sync(scr + mi * 16 * 68 + ni * 16, c[mi][ni], 68, wmma::mem_row_major);
    __syncwarp();

#pragma unroll
    for (int cc = 0; cc < 2; cc++) {
        const int col = warp_n * 64 + cc * 32 + lane;
#pragma unroll
        for (int rr = 0; rr < 32; rr++) {
            const size_t row = (size_t)(bm0 + warp_m * 32 + rr);
            Cf[row * N_TOT + col] = scr[rr * 68 + cc * 32 + lane];
        }
    }
}

// GEMM2 mega-kernel: sen2 (80) + obj2 (80) + body2 (8) = 168 CTAs
__global__ __launch_bounds__(256)
void gemm2_all()
{
    extern __shared__ __align__(16) char smraw[];
    const int b = blockIdx.x;
    if (b < 80) {
        wmma_dev<512>(128, b * 128, g_hs_hi, g_hs_lo, g_w2s_hi, g_w2s_lo, g_sen, smraw);
    } else if (b < 160) {
        wmma_dev<128>(128, (b - 80) * 128, g_ho_hi, g_ho_lo, g_w2o_hi, g_w2o_lo, g_obj, smraw);
    } else {
        wmma_dev<256>(128, (b - 160) * 128, g_hb_hi, g_hb_lo, g_w2b_hi, g_w2b_lo, g_bod, smraw);
    }
}

// ============================ fp32 SGEMM (fc, K=688) ============================
template<int BM, int BN, int BK, int TM, int TN>
__global__ void sgemm_kernel(int M, int N, int K,
    const float* __restrict__ A, const float* __restrict__ B,
    float* __restrict__ C, int ldc,
    const float* __restrict__ sc, const float* __restrict__ sh)
{
    constexpr int THREADS = (BM / TM) * (BN / TN);
    __shared__ float As[BK][BM];
    __shared__ float Bs[BK][BN];
    const int tid = threadIdx.x;
    const int bn0 = blockIdx.x * BN;
    const int bm0 = blockIdx.y * BM;
    const int tx = tid % (BN / TN);
    const int ty = tid / (BN / TN);

    float acc[TM][TN];
#pragma unroll
    for (int i = 0; i < TM; i++)
#pragma unroll
        for (int j = 0; j < TN; j++) acc[i][j] = 0.f;

    constexpr int AV = BM * BK / 4 / THREADS;
    constexpr int BV = BN * BK / 4 / THREADS;

    for (int k0 = 0; k0 < K; k0 += BK) {
#pragma unroll
        for (int i = 0; i < AV; i++) {
            int idx = tid + i * THREADS;
            int r = idx / (BK / 4), c4 = idx % (BK / 4);
            float4 v = *reinterpret_cast<const float4*>(A + (size_t)(bm0 + r) * K + k0 + c4 * 4);
            As[c4 * 4 + 0][r] = v.x; As[c4 * 4 + 1][r] = v.y;
            As[c4 * 4 + 2][r] = v.z; As[c4 * 4 + 3][r] = v.w;
        }
#pragma unroll
        for (int i = 0; i < BV; i++) {
            int idx = tid + i * THREADS;
            int r = idx / (BK / 4), c4 = idx % (BK / 4);
            float4 v = *reinterpret_cast<const float4*>(B + (size_t)(bn0 + r) * K + k0 + c4 * 4);
            Bs[c4 * 4 + 0][r] = v.x; Bs[c4 * 4 + 1][r] = v.y;
            Bs[c4 * 4 + 2][r] = v.z; Bs[c4 * 4 + 3][r] = v.w;
        }
        __syncthreads();
#pragma unroll
        for (int kk = 0; kk < BK; kk++) {
            float a[TM], b[TN];
#pragma unroll
            for (int i = 0; i < TM; i += 4) {
                float4 v = *reinterpret_cast<const float4*>(&As[kk][ty * TM + i]);
                a[i] = v.x; a[i + 1] = v.y; a[i + 2] = v.z; a[i + 3] = v.w;
            }
#pragma unroll
            for (int j = 0; j < TN; j += 4) {
                float4 v = *reinterpret_cast<const float4*>(&Bs[kk][tx * TN + j]);
                b[j] = v.x; b[j + 1] = v.y; b[j + 2] = v.z; b[j + 3] = v.w;
            }
#pragma unroll
            for (int i = 0; i < TM; i++)
#pragma unroll
                for (int j = 0; j < TN; j++)
                    acc[i][j] = fmaf(a[i], b[j], acc[i][j]);
        }
        __syncthreads();
    }
#pragma unroll
    for (int i = 0; i < TM; i++) {
        int row = bm0 + ty * TM + i;
#pragma unroll
        for (int j = 0; j < TN; j++) {
            int col = bn0 + tx * TN + j;
            float v = acc[i][j];
            if (sc) v = fmaxf(fmaf(v, sc[col], sh[col]), 0.f);
            C[(size_t)row * ldc + col] = v;
        }
    }
}

// ============================ fused attention stage ============================
__global__ void attention_kernel(
    const float* __restrict__ bbox, const float* __restrict__ word,
    const float* __restrict__ Wc1, const float* __restrict__ Wc2,
    const float* __restrict__ Wsa)
{
    __shared__ float xt[10][688];
    __shared__ float rmean[10], rmax[10], att[10];
    __shared__ float csum[688], cmax[688];

    const int b = blockIdx.x;
    const int tid = threadIdx.x;

    for (int idx = tid; idx < 10 * 688; idx += blockDim.x) {
        int n = idx / 688, f = idx % 688;
        int rn = b * 10 + n;
        float v;
        if (f < 128)       v = g_obj[rn * 128 + f];
        else if (f < 132)  v = bbox[rn * 4 + (f - 128)];
        else if (f < 432)  v = word[rn * 300 + (f - 132)];
        else if (f < 560)  v = g_sen[rn * 128 + (f - 432)];
        else               v = g_bod[b * 128 + (f - 560)];
        xt[n][f] = v;
    }
    __syncthreads();

    int w = tid / 32, lane = tid % 32;
    if (w < 10) {
        float s = 0.f, mx = -3.402823e38f;
        for (int f = lane; f < 688; f += 32) {
            float v = xt[w][f];
            s += v; mx = fmaxf(mx, v);
        }
#pragma unroll
        for (int o = 16; o; o >>= 1) {
            s += __shfl_down_sync(0xffffffff, s, o);
            mx = fmaxf(mx, __shfl_down_sync(0xffffffff, mx, o));
        }
        if (lane == 0) { rmean[w] = s * (1.f / 688.f); rmax[w] = mx; }
    }
    __syncthreads();

    if (tid == 0) {
        float h[5], o1[10], o2[10];
        for (int j = 0; j < 5; j++) {
            float s = 0.f;
            for (int i = 0; i < 10; i++) s += rmean[i] * Wc1[j * 10 + i];
            h[j] = fmaxf(s, 0.f);
        }
        for (int n = 0; n < 10; n++) {
            float s = 0.f;
            for (int j = 0; j < 5; j++) s += h[j] * Wc2[n * 5 + j];
            o1[n] = s;
        }
        for (int j = 0; j < 5; j++) {
            float s = 0.f;
            for (int i = 0; i < 10; i++) s += rmax[i] * Wc1[j * 10 + i];
            h[j] = fmaxf(s, 0.f);
        }
        for (int n = 0; n < 10; n++) {
            float s = 0.f;
            for (int j = 0; j < 5; j++) s += h[j] * Wc2[n * 5 + j];
            o2[n] = s;
        }
        for (int n = 0; n < 10; n++)
            att[n] = 1.f / (1.f + expf(-(o1[n] + o2[n])));
    }
    __syncthreads();

    for (int f = tid; f < 688; f += blockDim.x) {
        float s = 0.f, mx = -3.402823e38f;
#pragma unroll
        for (int n = 0; n < 10; n++) {
            float v = xt[n][f] * att[n];
            s += v; mx = fmaxf(mx, v);
        }
        csum[f] = s; cmax[f] = mx;
    }
    __syncthreads();

    for (int f = tid; f < 688; f += blockDim.x) {
        float sa = 0.f;
#pragma unroll
        for (int j = 0; j < 7; j++) {
            int p = f + j - 3;
            if (p >= 0 && p < 688)
                sa += Wsa[j] * (csum[p] * 0.1f) + Wsa[7 + j] * cmax[p];
        }
        float sig = 1.f / (1.f + expf(-sa));
        g_xs[b * 688 + f] = csum[f] * sig;
    }
}

// ============================ launch ============================
extern "C" void kernel_launch(void* const* d_in, const int* in_sizes, int n_in,
                              void* d_out, int out_size)
{
    const float* feat  = (const float*)d_in[0];
    const float* bbox  = (const float*)d_in[1];
    const float* word  = (const float*)d_in[2];
    const float* sent  = (const float*)d_in[3];
    const float* body  = (const float*)d_in[4];
    const float* W1_o  = (const float*)d_in[5];
    const float* go = (const float*)d_in[6],  *bo = (const float*)d_in[7];
    const float* mo = (const float*)d_in[8],  *vo = (const float*)d_in[9];
    const float* W2_o  = (const float*)d_in[10];
    const float* W1_s  = (const float*)d_in[11];
    const float* gs = (const float*)d_in[12], *bs = (const float*)d_in[13];
    const float* ms = (const float*)d_in[14], *vs = (const float*)d_in[15];
    const float* W2_s  = (const float*)d_in[16];
    const float* W1_b  = (const float*)d_in[17];
    const float* gb = (const float*)d_in[18], *bb = (const float*)d_in[19];
    const float* mb = (const float*)d_in[20], *vb = (const float*)d_in[21];
    const float* W2_b  = (const float*)d_in[22];
    const float* Wc1   = (const float*)d_in[23];
    const float* Wc2   = (const float*)d_in[24];
    const float* Wsa   = (const float*)d_in[25];
    const float* Wf    = (const float*)d_in[26];
    const float* bias_f= (const float*)d_in[27];
    const float* gf = (const float*)d_in[28], *bfv = (const float*)d_in[29];
    const float* mf = (const float*)d_in[30], *vf = (const float*)d_in[31];

    float *xs, *bnf_s, *bnf_t;
    cudaGetSymbolAddress((void**)&xs, g_xs);
    cudaGetSymbolAddress((void**)&bnf_s, g_bnf_s);
    cudaGetSymbolAddress((void**)&bnf_t, g_bnf_t);

    const int SMF = 4 * (64 * 72 * 2) + 4 * (128 * 72 * 2);  // 110592 B -> 2 CTAs/SM
    const int SMB = 8 * (128 * 72 * 2);                      // 147456 B
    cudaFuncSetAttribute(gemm1_all, cudaFuncAttributeMaxDynamicSharedMemorySize, SMF);
    cudaFuncSetAttribute(gemm2_all, cudaFuncAttributeMaxDynamicSharedMemorySize, SMB);

    prep_bn_kernel<<<1, 512>>>(gs, bs, ms, vs, go, bo, mo, vo,
                               gb, bb, mb, vb, gf, bfv, mf, vf, bias_f);

    split_all<<<2800, 256>>>((const float4*)W1_s, (const float4*)W2_s,
                             (const float4*)W1_o, (const float4*)W2_o,
                             (const float4*)W1_b, (const float4*)W2_b);

    // gemm1: 1280 sen halves + 32 body + 160 obj = 1472 CTAs (64-row tiles)
    gemm1_all<<<1472, 256, SMF>>>(sent, feat, body);
    reduce_sen<<<(10240 * 512 / 4 + 255) / 256, 256>>>();

    gemm2_all<<<168, 256, SMB>>>();

    attention_kernel<<<1024, 320>>>(bbox, word, Wc1, Wc2, Wsa);

    // fc: [1024,688] @ [688,256] + bias + BN + relu — 128 CTAs
    sgemm_kernel<32, 64, 16, 4, 4><<<dim3(256 / 64, 1024 / 32), 128>>>(
        1024, 256, 688, xs, Wf, (float*)d_out, 256, bnf_s, bnf_t);
}